// round 5
// baseline (speedup 1.0000x reference)
#include <cuda_runtime.h>
#include <math.h>

#define BIMG 4
#define HIMG 80
#define WIMG 80
#define HP   74
#define IMGPIX (HIMG*WIMG)
#define NPIX (BIMG*IMGPIX)

// c = -1/(2*2.5^2) * log2(e)   (exp -> exp2)
#define NEG_C2 (-0.11541560327111707f)
#define M2C    ( 0.23083120654223414f)   // -2*NEG_C2
// 1 / (49 * sqrt(2*pi*2.5^2))
#define KDE_SCALE 3.2566726960192768e-03f
// -ln2 / 49  (sum of lg2 -> -mean of ln)
#define NEG_LN2_49 (-1.4145860827753985e-02f)

__device__ float g_div[NPIX];
__device__ float g_W[BIMG * 49 * IMGPIX];   // W[b][r*7+c][Y][X]

__device__ __forceinline__ float ex2f(float x) {
    float y;
    asm("ex2.approx.f32 %0, %1;" : "=f"(y) : "f"(x));
    return y;
}

// ---------------------------------------------------------------------------
// K1: blur(5x5,zero-pad)/round -> sharp -> division; also zero d_out.
// ---------------------------------------------------------------------------
__global__ void preprocess_kernel(const float* __restrict__ x,
                                  float* __restrict__ out) {
    int idx = blockIdx.x * blockDim.x + threadIdx.x;
    if (idx >= NPIX) return;
    out[idx] = 0.0f;

    int b   = idx / IMGPIX;
    int rem = idx - b * IMGPIX;
    int y   = rem / WIMG;
    int xx  = rem - y * WIMG;
    const float* img = x + b * IMGPIX;

    float sum = 0.0f;
    #pragma unroll
    for (int dy = -2; dy <= 2; dy++) {
        int yy = y + dy;
        if ((unsigned)yy >= HIMG) continue;
        #pragma unroll
        for (int dx = -2; dx <= 2; dx++) {
            int xc = xx + dx;
            if ((unsigned)xc < WIMG) sum = __fadd_rn(sum, img[yy * WIMG + xc]);
        }
    }
    float smooth = rintf(__fdiv_rn(sum, 25.0f));
    float cv     = img[y * WIMG + xx];
    float sharp  = rintf(fminf(fmaxf(
                      __fsub_rn(__fmul_rn(2.5f, cv), __fmul_rn(1.25f, smooth)),
                      0.0f), 255.0f));
    float divi   = rintf(fminf(fmaxf(
                      __fdiv_rn(__fmul_rn(sharp, 255.0f),
                                __fadd_rn(smooth, 1e-8f)),
                      0.0f), 255.0f));
    g_div[idx] = divi;
}

// ---------------------------------------------------------------------------
// K2: per pixel (Y,X) build all 49 window role-sums W(r,c) via separable
// prefix sums over its 13x13 KDE neighborhood. Block = (Y, b), 512 threads.
//   stage A: item (dy,X): 13 exps over dx, running prefix -> A[(X,dy)][1..13]
//   stage B: item (c, X): row-sums via prefix-diff, prefix over dy,
//            W(r,c) = wpref[13-r]-wpref[6-r], store to g_W.
// OOB neighbors contribute exactly 0 (only invalid roles see them anyway).
// ---------------------------------------------------------------------------
#define DVP_STRIDE 81
#define SMEM_K2 ((13*DVP_STRIDE)*8 + (1040*13)*4)   // dvp + A = 62504 B

__global__ __launch_bounds__(512)
void build_w_kernel() {
    extern __shared__ char smraw[];
    float2* dvp = (float2*)smraw;                   // [13][81]: (v, NEG_C2*v*v)
    float*  A   = (float*)(smraw + 13 * DVP_STRIDE * 8);  // [1040][13]

    const int tid = threadIdx.x;
    const int Y   = blockIdx.x;        // 0..79
    const int b   = blockIdx.y;        // 0..3
    const float* dv = g_div + b * IMGPIX;

    // load 13 rows (Y-6..Y+6), OOB rows as zeros (masked later anyway)
    for (int i = tid; i < 13 * WIMG; i += 512) {
        int r = i / WIMG, c = i - r * WIMG;
        int row = Y - 6 + r;
        float v = ((unsigned)row < HIMG) ? dv[row * WIMG + c] : 0.0f;
        dvp[r * DVP_STRIDE + c] = make_float2(v, NEG_C2 * v * v);
    }
    __syncthreads();

    // -- stage A ------------------------------------------------------------
    for (int it = tid; it < 13 * WIMG; it += 512) {
        int dy = it / WIMG;
        int X  = it - dy * WIMG;
        int Yrow = Y - 6 + dy;
        bool rowok = ((unsigned)Yrow < HIMG);

        float2 ctr = dvp[6 * DVP_STRIDE + X];
        float pa = ctr.y;
        float ma = M2C * ctr.x;

        float* Ai = A + (X * 13 + dy) * 13;
        float run = 0.0f;
        #pragma unroll
        for (int dx = 0; dx < 13; dx++) {
            int x2 = X + dx - 6;
            float e = 0.0f;
            if (rowok && (unsigned)x2 < WIMG) {
                float2 nb = dvp[dy * DVP_STRIDE + x2];
                float arg = fmaf(ma, nb.x, pa + nb.y);
                e = ex2f(arg);
            }
            run += e;
            Ai[dx] = run;            // px[k=dx+1]; px[0] == 0 implicit
        }
    }
    __syncthreads();

    // -- stage B ------------------------------------------------------------
    for (int it = tid; it < 7 * WIMG; it += 512) {
        int c = it / WIMG;
        int X = it - c * WIMG;
        int hi = 12 - c;             // A index of px[13-c]
        int lo = 5 - c;              // A index of px[6-c]; -1 when c==6

        float wpref[14];
        wpref[0] = 0.0f;
        #pragma unroll
        for (int dy = 0; dy < 13; dy++) {
            const float* Ai = A + (X * 13 + dy) * 13;
            float rs = Ai[hi] - ((lo >= 0) ? Ai[lo] : 0.0f);
            wpref[dy + 1] = wpref[dy] + rs;
        }
        float* Wp = g_W + ((b * 49 + c) * HIMG + Y) * WIMG + X;
        #pragma unroll
        for (int r = 0; r < 7; r++) {
            // plane index r*7 + c  ->  offset r*7*IMGPIX from base (b,0+c)
            Wp[r * 7 * IMGPIX] = wpref[13 - r] - wpref[6 - r];
        }
    }
}

// ---------------------------------------------------------------------------
// K3: entropy per window. Block = (py, b), 224 threads: 3 threads per window
// (74*3 = 222 active), each sums lg2(p*scale+eps) over its element slice,
// deterministic 3-way combine via smem.
// ---------------------------------------------------------------------------
__global__ __launch_bounds__(224)
void entropy_kernel(float* __restrict__ out) {
    __shared__ float red[224];

    const int tid = threadIdx.x;
    const int py  = blockIdx.x;     // 0..73
    const int b   = blockIdx.y;
    const float* Wb = g_W + b * 49 * IMGPIX;

    float acc = 0.0f;
    int px = tid / 3;
    int part = tid - px * 3;
    if (tid < 222) {
        int i0 = part * 16;
        int i1 = (part == 2) ? 49 : (i0 + 16);
        for (int i = i0; i < i1; i++) {
            int r = i / 7;
            int c = i - r * 7;
            float w = Wb[(i * HIMG + (py + r)) * WIMG + (px + c)];
            acc += __log2f(fmaf(w, KDE_SCALE, 1e-8f));
        }
    }
    red[tid] = acc;
    __syncthreads();

    if (tid < HP) {
        float tot = red[tid * 3] + red[tid * 3 + 1] + red[tid * 3 + 2];
        out[b * IMGPIX + (py + 3) * WIMG + (tid + 3)] = tot * NEG_LN2_49;
    }
}

// ---------------------------------------------------------------------------
extern "C" void kernel_launch(void* const* d_in, const int* in_sizes, int n_in,
                              void* d_out, int out_size) {
    const float* x = (const float*)d_in[0];
    float* out     = (float*)d_out;

    cudaFuncSetAttribute(build_w_kernel,
                         cudaFuncAttributeMaxDynamicSharedMemorySize, SMEM_K2);

    preprocess_kernel<<<(NPIX + 255) / 256, 256>>>(x, out);
    build_w_kernel<<<dim3(HIMG, BIMG), 512, SMEM_K2>>>();
    entropy_kernel<<<dim3(HP, BIMG), 224>>>(out);
}

// round 6
// speedup vs baseline: 1.5569x; 1.5569x over previous
#include <cuda_runtime.h>
#include <math.h>

#define BIMG 4
#define HP   74
#define IMGPIX 6400
#define BT   640

// 1 / (49 * sqrt(2*pi*2.5^2))
#define KDE_SCALE 3.2566726960192768e-03f
// -log2(e) / (2*2.5^2)
#define NEG_C2 (-0.11541560327111707f)
// -ln2 / 49
#define NEG_LN2_49 (-1.4145860827753985e-02f)

// shared floats: xs[12*80] | dv[8*80] | S[2*7280] | L[2*3920] | red[640]
#define F_XS  0
#define F_DV  960
#define F_S   1600
#define F_L   16160
#define F_RED 24000
#define SMEM_BYTES ((24000 + 640) * 4)

__device__ __forceinline__ float ex2f(float x) {
    float y;
    asm("ex2.approx.f32 %0, %1;" : "=f"(y) : "f"(x));
    return y;
}

// ---------------------------------------------------------------------------
// One block per (band pair g, image b): output rows py0+3, py0+4 (py0 = 2g).
// Phases:
//  1) load input rows py0-2..py0+9 (zero-padded), zero S
//  2) blur/round -> sharp -> division for dv rows py0..py0+7
//     (op order identical to the R4 kernel: exact-rounding semantics)
//  3) symmetric column-sum KDE tables for BOTH bands from shared 8x8
//     row-pair exps: thread (xp, dc<=6) computes 64 exps once, accumulates
//     s0/t0 (band0: rows 0..6) and s1/t1 (band1: rows 1..7)
//  4) prefix over dc -> 7 window sums per (band,r,xp) -> log2 -> L
//  5) entropy per window: 4 threads/window, deterministic combine; borders
// ---------------------------------------------------------------------------
__global__ __launch_bounds__(BT, 1)
void entropy_pair_kernel(const float* __restrict__ x, float* __restrict__ out) {
    extern __shared__ float sm[];
    float* xs  = sm + F_XS;
    float* dv  = sm + F_DV;
    float* S   = sm + F_S;     // [band][(r*80+xp)*13 + dc]
    float* L   = sm + F_L;     // [band][(r*7+c)*80 + xp]
    float* red = sm + F_RED;

    const int tid = threadIdx.x;
    const int g   = blockIdx.x;        // 0..36
    const int b   = blockIdx.y;        // 0..3
    const int py0 = 2 * g;
    const float* img = x + b * IMGPIX;
    float* ob = out + b * IMGPIX;

    // -- 1: zero S + load input rows ----------------------------------------
    {
        float4* S4 = (float4*)S;
        for (int i = tid; i < 14560 / 4; i += BT)
            S4[i] = make_float4(0.f, 0.f, 0.f, 0.f);
    }
    for (int i = tid; i < 960; i += BT) {
        int r = i / 80, c = i - (i / 80) * 80;
        int row = py0 - 2 + r;
        xs[i] = ((unsigned)row < 80u) ? img[row * 80 + c] : 0.0f;
    }
    __syncthreads();

    // -- 2: preprocessing (exact op order; dv values are small integers) -----
    {
        int r = tid / 80, c = tid - (tid / 80) * 80;   // r = 0..7
        float sum = 0.0f;
        #pragma unroll
        for (int dy = 0; dy < 5; dy++) {
            const float* rowp = xs + (r + dy) * 80;
            #pragma unroll
            for (int dx = -2; dx <= 2; dx++) {
                int cc = c + dx;
                if ((unsigned)cc < 80u) sum = __fadd_rn(sum, rowp[cc]);
            }
        }
        float smooth = rintf(__fdiv_rn(sum, 25.0f));
        float cv     = xs[(r + 2) * 80 + c];
        float sharp  = rintf(fminf(fmaxf(
                          __fsub_rn(__fmul_rn(2.5f, cv), __fmul_rn(1.25f, smooth)),
                          0.0f), 255.0f));
        float divi   = rintf(fminf(fmaxf(
                          __fdiv_rn(__fmul_rn(sharp, 255.0f),
                                    __fadd_rn(smooth, 1e-8f)),
                          0.0f), 255.0f));
        dv[tid] = divi;
    }
    __syncthreads();

    // -- 3: shared KDE column sums for both bands ----------------------------
    if (tid < 560) {
        int dc = tid / 80;             // 0..6
        int xp = tid - dc * 80;        // 0..79
        int xc = xp - 6 + dc;          // <= xp
        if (xc >= 0) {
            float vA[8];
            #pragma unroll
            for (int a = 0; a < 8; a++) vA[a] = dv[a * 80 + xp];
            float s0[7], t0[7], s1[7], t1[7];
            #pragma unroll
            for (int r = 0; r < 7; r++) { s0[r] = t0[r] = s1[r] = t1[r] = 0.f; }
            #pragma unroll
            for (int bb = 0; bb < 8; bb++) {
                float vb = dv[bb * 80 + xc];
                #pragma unroll
                for (int a = 0; a < 8; a++) {
                    float d = vA[a] - vb;
                    float e = ex2f(d * d * NEG_C2);
                    if (a < 7 && bb < 7) { s0[a] += e; t0[bb] += e; }
                    if (a > 0 && bb > 0) { s1[a - 1] += e; t1[bb - 1] += e; }
                }
            }
            #pragma unroll
            for (int r = 0; r < 7; r++) {
                S[(r * 80 + xp) * 13 + dc]        = s0[r];
                S[7280 + (r * 80 + xp) * 13 + dc] = s1[r];
            }
            if (dc < 6) {              // mirror: column xc, offset 12-dc
                #pragma unroll
                for (int r = 0; r < 7; r++) {
                    S[(r * 80 + xc) * 13 + (12 - dc)]        = t0[r];
                    S[7280 + (r * 80 + xc) * 13 + (12 - dc)] = t1[r];
                }
            }
        }
    }
    __syncthreads();

    // -- 4: window sums via prefix, then log2 --------------------------------
    for (int it = tid; it < 1120; it += BT) {
        int h  = it / 560;
        int rr = it - h * 560;         // r*80 + xp
        const float* Sp = S + h * 7280 + rr * 13;
        float pref[14];
        pref[0] = 0.0f;
        #pragma unroll
        for (int k = 0; k < 13; k++) pref[k + 1] = pref[k] + Sp[k];
        int r = rr / 80, xp = rr - (rr / 80) * 80;
        float* Lh = L + h * 3920;
        #pragma unroll
        for (int c = 0; c < 7; c++) {
            float W = pref[13 - c] - pref[6 - c];   // >= 1 for valid windows
            Lh[(r * 7 + c) * 80 + xp] = __log2f(fmaf(W, KDE_SCALE, 1e-8f));
        }
    }
    __syncthreads();

    // -- 5: entropy per window (4 threads each), deterministic combine -------
    {
        float acc = 0.0f;
        if (tid < 592) {
            int w    = tid >> 2;               // 0..147
            int part = tid & 3;
            int h    = w / 74;
            int xw   = w - h * 74;
            const float* Lh = L + h * 3920;
            int i0 = part * 13;
            int i1 = (part == 3) ? 49 : i0 + 13;
            int r = i0 / 7, c = i0 - (i0 / 7) * 7;
            for (int i = i0; i < i1; i++) {
                acc += Lh[(r * 7 + c) * 80 + xw + c];
                if (++c == 7) { c = 0; r++; }
            }
        }
        red[tid] = acc;
    }
    __syncthreads();

    if (tid < 148) {
        int h  = tid / 74;
        int xw = tid - h * 74;
        float tot = red[tid * 4] + red[tid * 4 + 1]
                  + red[tid * 4 + 2] + red[tid * 4 + 3];
        ob[(py0 + h + 3) * 80 + (xw + 3)] = tot * NEG_LN2_49;
    }
    // column borders of the two written rows
    if (tid >= 160 && tid < 172) {
        int k = tid - 160;
        int h = k / 6, j = k - h * 6;
        int col = (j < 3) ? j : (74 + j);      // 0,1,2,77,78,79
        ob[(py0 + h + 3) * 80 + col] = 0.0f;
    }
    // top / bottom border rows
    if (g == 0  && tid < 240) ob[tid] = 0.0f;             // rows 0..2
    if (g == 36 && tid < 240) ob[77 * 80 + tid] = 0.0f;   // rows 77..79
}

// ---------------------------------------------------------------------------
extern "C" void kernel_launch(void* const* d_in, const int* in_sizes, int n_in,
                              void* d_out, int out_size) {
    const float* x = (const float*)d_in[0];
    float* out     = (float*)d_out;

    cudaFuncSetAttribute(entropy_pair_kernel,
                         cudaFuncAttributeMaxDynamicSharedMemorySize, SMEM_BYTES);
    dim3 grid(37, BIMG);               // 148 blocks = 1 per SM
    entropy_pair_kernel<<<grid, BT, SMEM_BYTES>>>(x, out);
}

// round 7
// speedup vs baseline: 1.6199x; 1.0405x over previous
#include <cuda_runtime.h>
#include <math.h>

#define BIMG 4
#define HP   74
#define IMGPIX 6400
#define BT   640

// 1 / (49 * sqrt(2*pi*2.5^2))
#define KDE_SCALE 3.2566726960192768e-03f
// sqrt(log2(e) / (2*2.5^2)): arg = -(d*S)^2 == d^2 * NEG_C2
#define SCALE_S 0.33972874f
// -ln2 / 49
#define NEG_LN2_49 (-1.4145860827753985e-02f)

// shared floats: xs[12*80] | dvs[8*80] | S[2*7280] | L[2*3920] | red[640]
#define F_XS  0
#define F_DV  960
#define F_S   1600
#define F_L   16160
#define F_RED 24000
#define SMEM_BYTES ((24000 + 640) * 4)

__device__ __forceinline__ float ex2f(float x) {
    float y;
    asm("ex2.approx.f32 %0, %1;" : "=f"(y) : "f"(x));
    return y;
}

// ---------------------------------------------------------------------------
// One block per (band pair g, image b): output rows py0+3, py0+4 (py0 = 2g).
//  1) load input rows py0-2..py0+9 (float4, zero-padded), zero S
//  2) blur/round -> sharp -> division (exact op order), stored PRE-SCALED
//  3) KDE column sums for both bands via 8x8 row-pair exps, marginal
//     accumulation (U/V) + boundary corrections: 3 arith + 2 add per exp
//  4) prefix over dc -> window sums -> log2 -> L
//  5) entropy per window (4 threads each), deterministic combine; borders
// ---------------------------------------------------------------------------
__global__ __launch_bounds__(BT, 1)
void entropy_pair_kernel(const float* __restrict__ x, float* __restrict__ out) {
    extern __shared__ float sm[];
    float* xs  = sm + F_XS;
    float* dvs = sm + F_DV;    // pre-scaled division values
    float* S   = sm + F_S;     // [band][(r*80+xp)*13 + dc]
    float* L   = sm + F_L;     // [band][(r*7+c)*80 + xp]
    float* red = sm + F_RED;

    const int tid = threadIdx.x;
    const int g   = blockIdx.x;        // 0..36
    const int b   = blockIdx.y;        // 0..3
    const int py0 = 2 * g;
    const float* img = x + b * IMGPIX;
    float* ob = out + b * IMGPIX;

    // -- 1: zero S + load 12 input rows (float4; rows are 16B aligned) -------
    {
        float4* S4 = (float4*)S;
        for (int i = tid; i < 14560 / 4; i += BT)
            S4[i] = make_float4(0.f, 0.f, 0.f, 0.f);
    }
    {
        float4* xs4 = (float4*)xs;
        const float4* img4 = (const float4*)img;
        for (int i = tid; i < 240; i += BT) {     // 12 rows * 20 float4
            int r = i / 20, c4 = i - r * 20;
            int row = py0 - 2 + r;
            xs4[i] = ((unsigned)row < 80u) ? img4[row * 20 + c4]
                                           : make_float4(0.f, 0.f, 0.f, 0.f);
        }
    }
    __syncthreads();

    // -- 2: preprocessing (exact op order); store scaled ---------------------
    {
        int r = tid / 80, c = tid - (tid / 80) * 80;   // r = 0..7
        float sum = 0.0f;
        #pragma unroll
        for (int dy = 0; dy < 5; dy++) {
            const float* rowp = xs + (r + dy) * 80;
            #pragma unroll
            for (int dx = -2; dx <= 2; dx++) {
                int cc = c + dx;
                if ((unsigned)cc < 80u) sum = __fadd_rn(sum, rowp[cc]);
            }
        }
        float smooth = rintf(__fdiv_rn(sum, 25.0f));
        float cv     = xs[(r + 2) * 80 + c];
        float sharp  = rintf(fminf(fmaxf(
                          __fsub_rn(__fmul_rn(2.5f, cv), __fmul_rn(1.25f, smooth)),
                          0.0f), 255.0f));
        float divi   = rintf(fminf(fmaxf(
                          __fdiv_rn(__fmul_rn(sharp, 255.0f),
                                    __fadd_rn(smooth, 1e-8f)),
                          0.0f), 255.0f));
        dvs[tid] = __fmul_rn(divi, SCALE_S);
    }
    __syncthreads();

    // -- 3: shared KDE column sums for both bands (marginal accumulation) ----
    if (tid < 560) {
        int dc = tid / 80;             // 0..6
        int xp = tid - dc * 80;        // 0..79
        int xc = xp - 6 + dc;          // <= xp
        if (xc >= 0) {
            float vA[8];
            #pragma unroll
            for (int a = 0; a < 8; a++) vA[a] = dvs[a * 80 + xp];
            float U[8], V[8];
            #pragma unroll
            for (int a = 0; a < 8; a++) { U[a] = 0.f; V[a] = 0.f; }
            float eA7[7], eA0[8], eB0[8], eB7[7];   // boundary exps
            #pragma unroll
            for (int bb = 0; bb < 8; bb++) {
                float vb = dvs[bb * 80 + xc];
                #pragma unroll
                for (int a = 0; a < 8; a++) {
                    float d = vA[a] - vb;
                    float e = ex2f(d * (-d));       // = exp(-(d)^2), neg folds
                    U[a]  += e;
                    V[bb] += e;
                    if (bb == 7 && a < 7) eA7[a] = e;
                    if (bb == 0 && a > 0) eA0[a] = e;
                    if (a == 0 && bb > 0) eB0[bb] = e;
                    if (a == 7 && bb < 7) eB7[bb] = e;
                }
            }
            #pragma unroll
            for (int r = 0; r < 7; r++) {
                S[(r * 80 + xp) * 13 + dc]        = U[r]     - eA7[r];   // s0
                S[7280 + (r * 80 + xp) * 13 + dc] = U[r + 1] - eA0[r + 1]; // s1
            }
            if (dc < 6) {              // mirror: column xc, offset 12-dc
                #pragma unroll
                for (int r = 0; r < 7; r++) {
                    S[(r * 80 + xc) * 13 + (12 - dc)]        = V[r]     - eB7[r];   // t0
                    S[7280 + (r * 80 + xc) * 13 + (12 - dc)] = V[r + 1] - eB0[r + 1]; // t1
                }
            }
        }
    }
    __syncthreads();

    // -- 4: window sums via prefix, then log2 --------------------------------
    for (int it = tid; it < 1120; it += BT) {
        int h  = it / 560;
        int rr = it - h * 560;         // r*80 + xp
        const float* Sp = S + h * 7280 + rr * 13;
        float pref[14];
        pref[0] = 0.0f;
        #pragma unroll
        for (int k = 0; k < 13; k++) pref[k + 1] = pref[k] + Sp[k];
        int r = rr / 80, xp = rr - (rr / 80) * 80;
        float* Lh = L + h * 3920;
        #pragma unroll
        for (int c = 0; c < 7; c++) {
            float W = pref[13 - c] - pref[6 - c];   // >= 1 for valid windows
            Lh[(r * 7 + c) * 80 + xp] = __log2f(fmaf(W, KDE_SCALE, 1e-8f));
        }
    }
    __syncthreads();

    // -- 5: entropy per window (4 threads each), deterministic combine -------
    {
        float acc = 0.0f;
        if (tid < 592) {
            int w    = tid >> 2;               // 0..147
            int part = tid & 3;
            int h    = w / 74;
            int xw   = w - h * 74;
            const float* Lh = L + h * 3920;
            int i0 = part * 13;
            int i1 = (part == 3) ? 49 : i0 + 13;
            int r = i0 / 7, c = i0 - (i0 / 7) * 7;
            for (int i = i0; i < i1; i++) {
                acc += Lh[(r * 7 + c) * 80 + xw + c];
                if (++c == 7) { c = 0; r++; }
            }
        }
        red[tid] = acc;
    }
    __syncthreads();

    if (tid < 148) {
        int h  = tid / 74;
        int xw = tid - h * 74;
        float tot = red[tid * 4] + red[tid * 4 + 1]
                  + red[tid * 4 + 2] + red[tid * 4 + 3];
        ob[(py0 + h + 3) * 80 + (xw + 3)] = tot * NEG_LN2_49;
    }
    // column borders of the two written rows
    if (tid >= 160 && tid < 172) {
        int k = tid - 160;
        int h = k / 6, j = k - h * 6;
        int col = (j < 3) ? j : (74 + j);      // 0,1,2,77,78,79
        ob[(py0 + h + 3) * 80 + col] = 0.0f;
    }
    // top / bottom border rows
    if (g == 0  && tid < 240) ob[tid] = 0.0f;             // rows 0..2
    if (g == 36 && tid < 240) ob[77 * 80 + tid] = 0.0f;   // rows 77..79
}

// ---------------------------------------------------------------------------
extern "C" void kernel_launch(void* const* d_in, const int* in_sizes, int n_in,
                              void* d_out, int out_size) {
    const float* x = (const float*)d_in[0];
    float* out     = (float*)d_out;

    cudaFuncSetAttribute(entropy_pair_kernel,
                         cudaFuncAttributeMaxDynamicSharedMemorySize, SMEM_BYTES);
    dim3 grid(37, BIMG);               // 148 blocks = 1 per SM
    entropy_pair_kernel<<<grid, BT, SMEM_BYTES>>>(x, out);
}